// round 1
// baseline (speedup 1.0000x reference)
#include <cuda_runtime.h>
#include <math_constants.h>

// ---------------- static device scratch (no runtime allocation) ----------------
__device__ float g_K     [64u*196*960];   // [b*4+h][196][960]
__device__ float g_Vt    [64u*960*196];   // [b*4+h][960][196]
__device__ float g_Qt    [64u*512*196];   // [z][c][196]   (max c = 512)
__device__ float g_scores[64u*512*960];   // [z][c][960]
__device__ float g_ctx   [64u*512*196];   // [z][c][196]
__device__ float g_ctxm  [16u*196*512];   // [b][n][c]
__device__ float g_mean  [64];
__device__ float g_invstd[64];
__device__ float g_partial[64*16*2];
__device__ float g_rowmax [64*512];
__device__ float g_rowoff [64*512];
__device__ float g_rowrinv[64*512];

#define BM 64
#define BN 64
#define BK 8

// ---------------- C[M,N] = alpha * A[M,K] * B[N,K]^T   (all row-major) ----------
__device__ __forceinline__ void sgemm_abT(const float* __restrict__ A,
                                          const float* __restrict__ B,
                                          float* __restrict__ C,
                                          int M, int N, int K,
                                          int lda, int ldb, int ldc, float alpha)
{
    __shared__ float As[BK][BM + 1];
    __shared__ float Bs[BK][BN + 1];
    const int tid = threadIdx.x;
    const int tx = tid & 15, ty = tid >> 4;
    const int row0 = blockIdx.y * BM, col0 = blockIdx.x * BN;
    float acc[4][4] = {};

    for (int k0 = 0; k0 < K; k0 += BK) {
#pragma unroll
        for (int i = 0; i < 2; i++) {
            int idx = tid * 2 + i;
            int r  = idx >> 3, kk = idx & 7;
            int gr = row0 + r, gk = k0 + kk;
            As[kk][r] = (gr < M && gk < K) ? A[(size_t)gr * lda + gk] : 0.f;
            int gn = col0 + r;  // reuse r as B's n-index (same tile shape)
            Bs[kk][r] = (gn < N && gk < K) ? B[(size_t)gn * ldb + gk] : 0.f;
        }
        __syncthreads();
#pragma unroll
        for (int kk = 0; kk < BK; kk++) {
            float a[4], b[4];
#pragma unroll
            for (int i = 0; i < 4; i++) a[i] = As[kk][ty * 4 + i];
#pragma unroll
            for (int j = 0; j < 4; j++) b[j] = Bs[kk][tx * 4 + j];
#pragma unroll
            for (int i = 0; i < 4; i++)
#pragma unroll
                for (int j = 0; j < 4; j++) acc[i][j] = fmaf(a[i], b[j], acc[i][j]);
        }
        __syncthreads();
    }
#pragma unroll
    for (int i = 0; i < 4; i++) {
        int gr = row0 + ty * 4 + i;
        if (gr >= M) continue;
#pragma unroll
        for (int j = 0; j < 4; j++) {
            int gc = col0 + tx * 4 + j;
            if (gc < N) C[(size_t)gr * ldc + gc] = alpha * acc[i][j];
        }
    }
}

// ---------------- C[M,N] = alpha * f(A[M,K]) * B[K,N]  (row-major) --------------
// If SOFT: f(x) = exp(x*inv_s - rowoff[row]) * rowrinv[row]  (fused softmax on A)
template <bool SOFT>
__device__ __forceinline__ void sgemm_ab(const float* __restrict__ A,
                                         const float* __restrict__ B,
                                         float* __restrict__ C,
                                         int M, int N, int K,
                                         int lda, int ldb, int ldc, float alpha,
                                         float inv_s,
                                         const float* __restrict__ rowoff,
                                         const float* __restrict__ rowrinv)
{
    __shared__ float As[BK][BM + 1];
    __shared__ float Bs[BK][BN + 1];
    const int tid = threadIdx.x;
    const int tx = tid & 15, ty = tid >> 4;
    const int row0 = blockIdx.y * BM, col0 = blockIdx.x * BN;
    float acc[4][4] = {};

    for (int k0 = 0; k0 < K; k0 += BK) {
#pragma unroll
        for (int i = 0; i < 2; i++) {
            int idx = tid * 2 + i;
            int r  = idx >> 3, kk = idx & 7;
            int gr = row0 + r, gk = k0 + kk;
            float v = 0.f;
            if (gr < M && gk < K) {
                v = A[(size_t)gr * lda + gk];
                if (SOFT) v = __expf(v * inv_s - rowoff[gr]) * rowrinv[gr];
            }
            As[kk][r] = v;
            int kk2 = idx >> 6, nn = idx & 63;
            int gk2 = k0 + kk2, gn = col0 + nn;
            Bs[kk2][nn] = (gk2 < K && gn < N) ? B[(size_t)gk2 * ldb + gn] : 0.f;
        }
        __syncthreads();
#pragma unroll
        for (int kk = 0; kk < BK; kk++) {
            float a[4], b[4];
#pragma unroll
            for (int i = 0; i < 4; i++) a[i] = As[kk][ty * 4 + i];
#pragma unroll
            for (int j = 0; j < 4; j++) b[j] = Bs[kk][tx * 4 + j];
#pragma unroll
            for (int i = 0; i < 4; i++)
#pragma unroll
                for (int j = 0; j < 4; j++) acc[i][j] = fmaf(a[i], b[j], acc[i][j]);
        }
        __syncthreads();
    }
#pragma unroll
    for (int i = 0; i < 4; i++) {
        int gr = row0 + ty * 4 + i;
        if (gr >= M) continue;
#pragma unroll
        for (int j = 0; j < 4; j++) {
            int gc = col0 + tx * 4 + j;
            if (gc < N) C[(size_t)gr * ldc + gc] = alpha * acc[i][j];
        }
    }
}

// ---------------- wrapper kernels -----------------------------------------------

// K[z][n][o] = sum_k emb_all[b][n][k] * Wk[h][o][k]
__global__ __launch_bounds__(256) void k_projK(const float* __restrict__ emb_all,
                                               const float* __restrict__ Wk)
{
    int z = blockIdx.z, b = z >> 2, h = z & 3;
    sgemm_abT(emb_all + (size_t)b * 196 * 960, Wk + (size_t)h * 960 * 960,
              g_K + (size_t)z * 196 * 960,
              196, 960, 960, 960, 960, 960, 1.f);
}

// Vt[z][o][n] = sum_k Wv[h][o][k] * emb_all[b][n][k]
__global__ __launch_bounds__(256) void k_projVt(const float* __restrict__ emb_all,
                                                const float* __restrict__ Wv)
{
    int z = blockIdx.z, b = z >> 2, h = z & 3;
    sgemm_abT(Wv + (size_t)h * 960 * 960, emb_all + (size_t)b * 196 * 960,
              g_Vt + (size_t)z * 960 * 196,
              960, 196, 960, 960, 960, 196, 1.f);
}

// Qt[z][d][n] = sum_c Wq[h][d][c] * emb[b][n][c]
__global__ __launch_bounds__(256) void k_projQt(const float* __restrict__ emb,
                                                const float* __restrict__ Wq, int c)
{
    int z = blockIdx.z, b = z >> 2, h = z & 3;
    sgemm_abT(Wq + (size_t)h * c * c, emb + (size_t)b * 196 * c,
              g_Qt + (size_t)z * c * 196,
              c, 196, c, c, c, 196, 1.f);
}

// scores[z][d][k] = (1/sqrt(960)) * sum_n Qt[z][d][n] * K[z][n][k]
__global__ __launch_bounds__(256) void k_scores(int c)
{
    int z = blockIdx.z;
    sgemm_ab<false>(g_Qt + (size_t)z * c * 196, g_K + (size_t)z * 196 * 960,
                    g_scores + (size_t)z * c * 960,
                    c, 960, 196, 196, 960, 960,
                    0.03227486121839514f, 0.f, nullptr, nullptr);
}

__global__ __launch_bounds__(256) void k_rowmax(int c)
{
    int row = blockIdx.x;  // z*c + d
    const float* p = g_scores + (size_t)row * 960;
    float m = -CUDART_INF_F;
    for (int i = threadIdx.x; i < 960; i += 256) m = fmaxf(m, p[i]);
    __shared__ float sm[256];
    sm[threadIdx.x] = m;
    __syncthreads();
    for (int s = 128; s > 0; s >>= 1) {
        if (threadIdx.x < s) sm[threadIdx.x] = fmaxf(sm[threadIdx.x], sm[threadIdx.x + s]);
        __syncthreads();
    }
    if (threadIdx.x == 0) g_rowmax[row] = sm[0];
}

__global__ __launch_bounds__(256) void k_stats_partial(int c)
{
    int z = blockIdx.y, s = blockIdx.x;
    int total = c * 960;
    int chunk = (total + 15) / 16;
    int start = s * chunk;
    int end = min(start + chunk, total);
    const float* p = g_scores + (size_t)z * total;
    float sum = 0.f, sq = 0.f;
    for (int i = start + threadIdx.x; i < end; i += 256) {
        float v = p[i];
        sum += v;
        sq  += v * v;
    }
    __shared__ float s1[256], s2[256];
    s1[threadIdx.x] = sum; s2[threadIdx.x] = sq;
    __syncthreads();
    for (int t = 128; t > 0; t >>= 1) {
        if (threadIdx.x < t) { s1[threadIdx.x] += s1[threadIdx.x + t];
                               s2[threadIdx.x] += s2[threadIdx.x + t]; }
        __syncthreads();
    }
    if (threadIdx.x == 0) {
        g_partial[(z * 16 + s) * 2 + 0] = s1[0];
        g_partial[(z * 16 + s) * 2 + 1] = s2[0];
    }
}

__global__ void k_stats_final(int c)
{
    int z = threadIdx.x;
    if (z >= 64) return;
    float sum = 0.f, sq = 0.f;
    for (int s = 0; s < 16; s++) {
        sum += g_partial[(z * 16 + s) * 2 + 0];
        sq  += g_partial[(z * 16 + s) * 2 + 1];
    }
    float n = (float)(c * 960);
    float m = sum / n;
    float var = sq / n - m * m;
    g_mean[z] = m;
    g_invstd[z] = rsqrtf(var + 1e-5f);
}

// Per row: off = rowmax*inv_s; rinv = 1/sum_k exp(x*inv_s - off).
// (InstanceNorm mean cancels inside softmax by shift-invariance.)
__global__ __launch_bounds__(256) void k_rowsoft(int c)
{
    int row = blockIdx.x;
    int z = row / c;
    float is = g_invstd[z];
    float off = g_rowmax[row] * is;
    const float* p = g_scores + (size_t)row * 960;
    float sm = 0.f;
    for (int i = threadIdx.x; i < 960; i += 256) sm += __expf(p[i] * is - off);
    __shared__ float s1[256];
    s1[threadIdx.x] = sm;
    __syncthreads();
    for (int t = 128; t > 0; t >>= 1) {
        if (threadIdx.x < t) s1[threadIdx.x] += s1[threadIdx.x + t];
        __syncthreads();
    }
    if (threadIdx.x == 0) {
        g_rowoff[row]  = off;
        g_rowrinv[row] = 1.f / s1[0];
    }
}

// ctx[z][d][n] = sum_k softmax(scores)[z][d][k] * Vt[z][k][n]   (softmax fused)
__global__ __launch_bounds__(256) void k_ctx(int c)
{
    int z = blockIdx.z;
    sgemm_ab<true>(g_scores + (size_t)z * c * 960, g_Vt + (size_t)z * 960 * 196,
                   g_ctx + (size_t)z * c * 196,
                   c, 196, 960, 960, 196, 196, 1.f,
                   g_invstd[z], g_rowoff + z * c, g_rowrinv + z * c);
}

// ctxm[b][n][d] = 0.25 * sum_h ctx[b*4+h][d][n]  (head-mean + transpose, tiled)
__global__ void k_meanT(int c)
{
    __shared__ float t[32][33];
    int b  = blockIdx.z;
    int d0 = blockIdx.y * 32, n0 = blockIdx.x * 32;
    int tx = threadIdx.x, ty = threadIdx.y;
    for (int i = ty; i < 32; i += 8) {
        int d = d0 + i, n = n0 + tx;
        float s = 0.f;
        if (n < 196) {
            for (int h = 0; h < 4; h++)
                s += g_ctx[((size_t)(b * 4 + h) * c + d) * 196 + n];
        }
        t[i][tx] = 0.25f * s;
    }
    __syncthreads();
    for (int i = ty; i < 32; i += 8) {
        int n = n0 + i, d = d0 + tx;
        if (n < 196) g_ctxm[((size_t)b * 196 + n) * c + d] = t[tx][i];
    }
}

// O[bn][e] = sum_d ctxm[bn][d] * Wo[e][d]
__global__ __launch_bounds__(256) void k_out(const float* __restrict__ Wo,
                                             float* __restrict__ out, int c)
{
    sgemm_abT(g_ctxm, Wo, out, 16 * 196, c, c, c, c, c, 1.f);
}

// ---------------- launch ---------------------------------------------------------
extern "C" void kernel_launch(void* const* d_in, const int* in_sizes, int n_in,
                              void* d_out, int out_size)
{
    (void)in_sizes; (void)n_in; (void)out_size;
    const float* emb[4]  = {(const float*)d_in[0], (const float*)d_in[1],
                            (const float*)d_in[2], (const float*)d_in[3]};
    const float* emb_all = (const float*)d_in[4];
    const float* Wq[4]   = {(const float*)d_in[5], (const float*)d_in[6],
                            (const float*)d_in[7], (const float*)d_in[8]};
    const float* Wk      = (const float*)d_in[9];
    const float* Wv      = (const float*)d_in[10];
    const float* Wo[4]   = {(const float*)d_in[11], (const float*)d_in[12],
                            (const float*)d_in[13], (const float*)d_in[14]};
    float* out = (float*)d_out;

    // shared K / Vt projections: M=196/960 per (b,h)
    k_projK <<<dim3(15, 4, 64), 256>>>(emb_all, Wk);   // N=960 -> 15 tiles, M=196 -> 4
    k_projVt<<<dim3(4, 15, 64), 256>>>(emb_all, Wv);   // N=196 -> 4,  M=960 -> 15

    const int Cs[4]   = {64, 128, 256, 512};
    const int offs[4] = {0, 16 * 196 * 64, 16 * 196 * (64 + 128),
                         16 * 196 * (64 + 128 + 256)};

    for (int br = 0; br < 4; br++) {
        int c = Cs[br];
        k_projQt<<<dim3(4, c / 64, 64), 256>>>(emb[br], Wq[br], c);
        k_scores<<<dim3(15, c / 64, 64), 256>>>(c);
        k_rowmax<<<64 * c, 256>>>(c);
        k_stats_partial<<<dim3(16, 64), 256>>>(c);
        k_stats_final<<<1, 64>>>(c);
        k_rowsoft<<<64 * c, 256>>>(c);
        k_ctx<<<dim3(4, c / 64, 64), 256>>>(c);
        k_meanT<<<dim3(7, c / 32, 16), dim3(32, 8)>>>(c);
        k_out<<<dim3((c + 63) / 64, 49, 1), 256>>>(Wo[br], out + offs[br], c);
    }
}

// round 2
// speedup vs baseline: 1.7606x; 1.7606x over previous
#include <cuda_runtime.h>
#include <math_constants.h>

// ---------------- static device scratch (no runtime allocation) ----------------
__device__ float g_K     [64u*196*960];   // [b*4+h][196][960]
__device__ float g_Vt    [64u*960*196];   // [b*4+h][960][196]
__device__ float g_Qt    [64u*512*196];   // [z][c][196]
__device__ float g_scores[64u*512*960];   // [z][c][960]
__device__ float g_ctx   [64u*512*196];   // [z][c][196]
__device__ float g_ctxm  [16u*196*512];   // [b][n][c]
__device__ float g_invstd[64];
__device__ float g_partial[64*32*2];
__device__ int   g_rowmaxi[64*512];
__device__ float g_rowoff [64*512];
__device__ float g_rowrinv[64*512];

#define BM 128
#define BN 128
#define BK 8
#define PAD 4

__device__ __forceinline__ int f2ord(float f) {
    int i = __float_as_int(f);
    return i >= 0 ? i : i ^ 0x7fffffff;
}
__device__ __forceinline__ float ord2f(int i) {
    return __int_as_float(i >= 0 ? i : i ^ 0x7fffffff);
}

// ---------------------------------------------------------------------------
// C[M,N] = alpha * f(A[M,K]) * opB
//   LAYB==0 : B is [N,K] row-major (i.e. C = A * B^T)
//   LAYB==1 : B is [K,N] row-major (i.e. C = A * B)
// SOFT : A elements transformed exp(a*inv_s - rowoff[r]) * rowrinv[r]
// STATS: epilogue emits per-row max (atomicMax, order-independent) and
//        per-block sum/sumsq partials for the InstanceNorm statistics.
// per-z operand offset = (z&3)*s_h + (z>>2)*s_b
// ---------------------------------------------------------------------------
template<int LAYB, bool SOFT, bool STATS>
__device__ __forceinline__ void gemm_body(
    const float* __restrict__ A, long sAh, long sAb, int lda,
    const float* __restrict__ B, long sBh, long sBb, int ldb,
    float* __restrict__ C, long sCh, long sCb, int ldc,
    int M, int N, int K, float alpha)
{
    __shared__ float As[BK][BM + PAD];
    __shared__ float Bs[BK][BN + PAD];
    const int z = blockIdx.z;
    const int h = z & 3, bb_ = z >> 2;
    A += (long)h * sAh + (long)bb_ * sAb;
    B += (long)h * sBh + (long)bb_ * sBb;
    C += (long)h * sCh + (long)bb_ * sCb;

    const int tid = threadIdx.x;
    const int tx = tid & 15, ty = tid >> 4;
    const int row0 = blockIdx.y * BM, col0 = blockIdx.x * BN;

    float inv_s = 0.f;
    const float* rowoff = nullptr;
    const float* rowrinv = nullptr;
    if (SOFT) {
        inv_s  = g_invstd[z];
        rowoff  = g_rowoff  + (size_t)z * M;
        rowrinv = g_rowrinv + (size_t)z * M;
    }

    // A tile loader mapping: 128 rows x 8 k, one float4 per thread
    const int arow  = tid >> 1;
    const int akseg = (tid & 1) * 4;
    const int agr   = row0 + arow;
    // B tile loader mapping
    const int brow  = tid >> 1;          // LAYB==0
    const int bkseg = (tid & 1) * 4;
    const int bkk   = tid >> 5;          // LAYB==1
    const int bn    = (tid & 31) * 4;

    float acc[8][8];
#pragma unroll
    for (int i = 0; i < 8; i++)
#pragma unroll
        for (int j = 0; j < 8; j++) acc[i][j] = 0.f;

    const int KT = (K + BK - 1) / BK;
    float4 av, bv;

    auto loadA = [&](int k0) {
        float4 v = make_float4(0.f, 0.f, 0.f, 0.f);
        int gk = k0 + akseg;
        if (agr < M && gk < K) {
            v = *reinterpret_cast<const float4*>(A + (size_t)agr * lda + gk);
            if (SOFT) {
                float ro = rowoff[agr], ri = rowrinv[agr];
                v.x = __expf(v.x * inv_s - ro) * ri;
                v.y = __expf(v.y * inv_s - ro) * ri;
                v.z = __expf(v.z * inv_s - ro) * ri;
                v.w = __expf(v.w * inv_s - ro) * ri;
            }
        }
        return v;
    };
    auto loadB = [&](int k0) {
        float4 v = make_float4(0.f, 0.f, 0.f, 0.f);
        if (LAYB == 0) {
            int gk = k0 + bkseg, gn = col0 + brow;
            if (gn < N && gk < K)
                v = *reinterpret_cast<const float4*>(B + (size_t)gn * ldb + gk);
        } else {
            int gk = k0 + bkk, gn = col0 + bn;
            if (gk < K && gn < N)
                v = *reinterpret_cast<const float4*>(B + (size_t)gk * ldb + gn);
        }
        return v;
    };
    auto storeS = [&]() {
        As[akseg + 0][arow] = av.x; As[akseg + 1][arow] = av.y;
        As[akseg + 2][arow] = av.z; As[akseg + 3][arow] = av.w;
        if (LAYB == 0) {
            Bs[bkseg + 0][brow] = bv.x; Bs[bkseg + 1][brow] = bv.y;
            Bs[bkseg + 2][brow] = bv.z; Bs[bkseg + 3][brow] = bv.w;
        } else {
            *reinterpret_cast<float4*>(&Bs[bkk][bn]) = bv;
        }
    };
    auto compute = [&]() {
#pragma unroll
        for (int kk = 0; kk < BK; kk++) {
            float a[8], bq[8];
            *reinterpret_cast<float4*>(a)      = *reinterpret_cast<const float4*>(&As[kk][ty * 8]);
            *reinterpret_cast<float4*>(a + 4)  = *reinterpret_cast<const float4*>(&As[kk][ty * 8 + 4]);
            *reinterpret_cast<float4*>(bq)     = *reinterpret_cast<const float4*>(&Bs[kk][tx * 8]);
            *reinterpret_cast<float4*>(bq + 4) = *reinterpret_cast<const float4*>(&Bs[kk][tx * 8 + 4]);
#pragma unroll
            for (int i = 0; i < 8; i++)
#pragma unroll
                for (int j = 0; j < 8; j++)
                    acc[i][j] = fmaf(a[i], bq[j], acc[i][j]);
        }
    };

    av = loadA(0); bv = loadB(0);
    storeS();
    __syncthreads();
    for (int t = 1; t < KT; t++) {
        av = loadA(t * BK); bv = loadB(t * BK);
        compute();
        __syncthreads();
        storeS();
        __syncthreads();
    }
    compute();

#pragma unroll
    for (int i = 0; i < 8; i++)
#pragma unroll
        for (int j = 0; j < 8; j++) acc[i][j] *= alpha;

    // store C (vectorized fast path when the 8-col strip is fully valid)
#pragma unroll
    for (int i = 0; i < 8; i++) {
        int gr = row0 + ty * 8 + i;
        if (gr >= M) continue;
        int gc0 = col0 + tx * 8;
        float* cp = C + (size_t)gr * ldc + gc0;
        if (gc0 + 7 < N) {
            *reinterpret_cast<float4*>(cp)     = *reinterpret_cast<float4*>(&acc[i][0]);
            *reinterpret_cast<float4*>(cp + 4) = *reinterpret_cast<float4*>(&acc[i][4]);
        } else {
#pragma unroll
            for (int j = 0; j < 8; j++)
                if (gc0 + j < N) cp[j] = acc[i][j];
        }
    }

    if (STATS) {
        float lsum = 0.f, lsq = 0.f;
#pragma unroll
        for (int i = 0; i < 8; i++) {
            float rm = -CUDART_INF_F;
            int gr = row0 + ty * 8 + i;
#pragma unroll
            for (int j = 0; j < 8; j++) {
                int gc = col0 + tx * 8 + j;
                if (gc < N) {
                    float v = acc[i][j];
                    lsum += v; lsq += v * v;
                    rm = fmaxf(rm, v);
                }
            }
            // reduce row-max across the 16 tx lanes owning this row strip
#pragma unroll
            for (int m = 1; m < 16; m <<= 1)
                rm = fmaxf(rm, __shfl_xor_sync(0xffffffffu, rm, m, 16));
            if (tx == 0 && gr < M)
                atomicMax(&g_rowmaxi[(size_t)z * M + gr], f2ord(rm));
        }
        __shared__ float s1[256], s2[256];
        s1[tid] = lsum; s2[tid] = lsq;
        __syncthreads();
        for (int s = 128; s > 0; s >>= 1) {
            if (tid < s) { s1[tid] += s1[tid + s]; s2[tid] += s2[tid + s]; }
            __syncthreads();
        }
        if (tid == 0) {
            int pb = (z * 32 + blockIdx.y * gridDim.x + blockIdx.x) * 2;
            g_partial[pb] = s1[0];
            g_partial[pb + 1] = s2[0];
        }
    }
}

// ---------------- wrapper kernels ------------------------------------------------

__global__ __launch_bounds__(256, 2) void k_projK(const float* __restrict__ emb_all,
                                                  const float* __restrict__ Wk)
{   // K[z][196][960] = emb_all[b] * Wk[h]^T
    gemm_body<0, false, false>(emb_all, 0, 196L * 960, 960,
                               Wk, 960L * 960, 0, 960,
                               g_K, 196L * 960, 4L * 196 * 960, 960,
                               196, 960, 960, 1.f);
}

__global__ __launch_bounds__(256, 2) void k_projVt(const float* __restrict__ emb_all,
                                                   const float* __restrict__ Wv)
{   // Vt[z][960][196] = Wv[h] * emb_all[b]^T
    gemm_body<0, false, false>(Wv, 960L * 960, 0, 960,
                               emb_all, 0, 196L * 960, 960,
                               g_Vt, 960L * 196, 4L * 960 * 196, 196,
                               960, 196, 960, 1.f);
}

__global__ __launch_bounds__(256, 2) void k_projQt(const float* __restrict__ emb,
                                                   const float* __restrict__ Wq, int c)
{   // Qt[z][c][196] = Wq[h] * emb[b]^T
    gemm_body<0, false, false>(Wq, (long)c * c, 0, c,
                               emb, 0, 196L * c, c,
                               g_Qt, (long)c * 196, 4L * c * 196, 196,
                               c, 196, c, 1.f);
}

__global__ __launch_bounds__(256, 2) void k_scores(int c)
{   // scores[z][c][960] = Qt[z] * K[z] / sqrt(960)   (+stats epilogue)
    gemm_body<1, false, true>(g_Qt, (long)c * 196, 4L * c * 196, 196,
                              g_K, 196L * 960, 4L * 196 * 960, 960,
                              g_scores, (long)c * 960, 4L * c * 960, 960,
                              c, 960, 196, 0.03227486121839514f);
}

__global__ __launch_bounds__(256, 2) void k_ctx(int c)
{   // ctx[z][c][196] = softmax(norm(scores))[z] * Vt[z]   (softmax fused on A)
    gemm_body<1, true, false>(g_scores, (long)c * 960, 4L * c * 960, 960,
                              g_Vt, 960L * 196, 4L * 960 * 196, 196,
                              g_ctx, (long)c * 196, 4L * c * 196, 196,
                              c, 196, 960, 1.f);
}

__global__ __launch_bounds__(256, 2) void k_out(const float* __restrict__ Wo,
                                                float* __restrict__ out, int c)
{   // O[bn][c] = ctxm[bn] * Wo^T
    gemm_body<0, false, false>(g_ctxm, 0, 0, c,
                               Wo, 0, 0, c,
                               out, 0, 0, c,
                               16 * 196, c, c, 1.f);
}

// ---------------- small kernels --------------------------------------------------

__global__ void k_initmax(int n)
{
    int i = blockIdx.x * 256 + threadIdx.x;
    if (i < n) g_rowmaxi[i] = 0x80000000;
}

__global__ void k_stats_final(int c, int nblk)
{
    int z = threadIdx.x;
    if (z >= 64) return;
    float sum = 0.f, sq = 0.f;
    for (int s = 0; s < nblk; s++) {
        sum += g_partial[(z * 32 + s) * 2 + 0];
        sq  += g_partial[(z * 32 + s) * 2 + 1];
    }
    float n = (float)c * 960.f;
    float m = sum / n;
    g_invstd[z] = rsqrtf(sq / n - m * m + 1e-5f);
}

// Per row: off = rowmax*inv_s ; rinv = 1/sum_k exp(x*inv_s - off).
// (InstanceNorm mean cancels inside softmax by shift-invariance.)
__global__ __launch_bounds__(256) void k_rowsoft(int c)
{
    int row = blockIdx.x;          // z*c + d
    int z = row / c;
    float is = g_invstd[z];
    float off = ord2f(g_rowmaxi[row]) * is;
    const float* p = g_scores + (size_t)row * 960;
    float sm = 0.f;
    for (int i = threadIdx.x; i < 960; i += 256) sm += __expf(p[i] * is - off);
    __shared__ float s1[256];
    s1[threadIdx.x] = sm;
    __syncthreads();
    for (int t = 128; t > 0; t >>= 1) {
        if (threadIdx.x < t) s1[threadIdx.x] += s1[threadIdx.x + t];
        __syncthreads();
    }
    if (threadIdx.x == 0) {
        g_rowoff[row]  = off;
        g_rowrinv[row] = 1.f / s1[0];
    }
}

// ctxm[b][n][d] = 0.25 * sum_h ctx[b*4+h][d][n]  (head-mean + transpose, tiled)
__global__ void k_meanT(int c)
{
    __shared__ float t[32][33];
    int b  = blockIdx.z;
    int d0 = blockIdx.y * 32, n0 = blockIdx.x * 32;
    int tx = threadIdx.x, ty = threadIdx.y;
    for (int i = ty; i < 32; i += 8) {
        int d = d0 + i, n = n0 + tx;
        float s = 0.f;
        if (n < 196) {
            for (int h = 0; h < 4; h++)
                s += g_ctx[((size_t)(b * 4 + h) * c + d) * 196 + n];
        }
        t[i][tx] = 0.25f * s;
    }
    __syncthreads();
    for (int i = ty; i < 32; i += 8) {
        int n = n0 + i, d = d0 + tx;
        if (n < 196) g_ctxm[((size_t)b * 196 + n) * c + d] = t[tx][i];
    }
}

// ---------------- launch ---------------------------------------------------------
extern "C" void kernel_launch(void* const* d_in, const int* in_sizes, int n_in,
                              void* d_out, int out_size)
{
    (void)in_sizes; (void)n_in; (void)out_size;
    const float* emb[4]  = {(const float*)d_in[0], (const float*)d_in[1],
                            (const float*)d_in[2], (const float*)d_in[3]};
    const float* emb_all = (const float*)d_in[4];
    const float* Wq[4]   = {(const float*)d_in[5], (const float*)d_in[6],
                            (const float*)d_in[7], (const float*)d_in[8]};
    const float* Wk      = (const float*)d_in[9];
    const float* Wv      = (const float*)d_in[10];
    const float* Wo[4]   = {(const float*)d_in[11], (const float*)d_in[12],
                            (const float*)d_in[13], (const float*)d_in[14]};
    float* out = (float*)d_out;

    k_projK <<<dim3(8, 2, 64), 256>>>(emb_all, Wk);   // N=960->8 tiles, M=196->2
    k_projVt<<<dim3(2, 8, 64), 256>>>(emb_all, Wv);   // N=196->2,  M=960->8

    const int Cs[4]   = {64, 128, 256, 512};
    const int offs[4] = {0, 16 * 196 * 64, 16 * 196 * (64 + 128),
                         16 * 196 * (64 + 128 + 256)};

    for (int br = 0; br < 4; br++) {
        int c = Cs[br];
        int my = (c + 127) / 128;       // M tiles for M=c
        k_projQt<<<dim3(2, my, 64), 256>>>(emb[br], Wq[br], c);
        k_initmax<<<(64 * c + 255) / 256, 256>>>(64 * c);
        k_scores<<<dim3(8, my, 64), 256>>>(c);
        k_stats_final<<<1, 64>>>(c, 8 * my);
        k_rowsoft<<<64 * c, 256>>>(c);
        k_ctx<<<dim3(2, my, 64), 256>>>(c);
        k_meanT<<<dim3(7, c / 32, 16), dim3(32, 8)>>>(c);
        k_out<<<dim3((c + 127) / 128, 25, 1), 256>>>(Wo[br], out + offs[br], c);
    }
}

// round 9
// speedup vs baseline: 1.9693x; 1.1185x over previous
#include <cuda_runtime.h>
#include <math_constants.h>
#include <cstdint>

// ---------------- static device scratch (no runtime allocation) ----------------
// Branch-concatenated layouts, cumc = {0,64,192,448}, total c = 960.
__device__ __align__(16) float g_K     [64u*196*960];   // [z][196][960]
__device__ __align__(16) float g_Vt    [64u*960*196];   // [z][960][196]
__device__ __align__(16) float g_Qt    [64u*960*196];   // per-branch [64][c][196] regions
__device__ __align__(16) float g_scores[64u*960*960];   // per-branch [64][c][960] regions
__device__ __align__(16) float g_ctx   [64u*960*196];   // per-branch [64][c][196] regions
__device__ __align__(16) float g_ctxm  [16u*196*960];   // per-branch [16][196][c] regions
__device__ float g_invstd [4*64];
__device__ float g_partial[4*64*32*2];
__device__ int   g_rowmaxi[64*960];                     // linear rows: base[br] + z*c + d

__device__ __forceinline__ int f2ord(float f) {
    int i = __float_as_int(f);
    return i >= 0 ? i : i ^ 0x7fffffff;
}
__device__ __forceinline__ float ord2f(int i) {
    return __int_as_float(i >= 0 ? i : i ^ 0x7fffffff);
}

#define BM 128
#define BN 128
#define BK 8
#define PAD 4

// ---------------- job table for merged GEMM launches ------------------------------
struct Jobs {
    const float* A[4]; const float* B[4]; float* C[4];
    long sAh[4], sAb[4], sBh[4], sBb[4], sCh[4], sCb[4];
    int  lda[4], ldb[4], ldc[4], M[4], N[4], K[4];
    float alpha[4];
    int  nx[4];      // tiles along N
    int  bx0[4];     // cumulative blockIdx.x start (unused: INT_MAX)
    int  rmoff[4];   // row-max base (row units)
};

// ---------------------------------------------------------------------------------
// C[M,N] = alpha * A[M,K] * opB  — proven round-2 scalar SGEMM core.
//   LAYB==0 : B is [N,K] row-major (C = A * B^T)
//   LAYB==1 : B is [K,N] row-major (C = A * B)
// STATS: epilogue row-max atomics + block sum/sumsq partials (InstanceNorm)
// ---------------------------------------------------------------------------------
template<int LAYB, bool STATS>
__device__ __forceinline__ void gemm_core(const Jobs& J, int br, int local, int zz)
{
    __shared__ float As[BK][BM + PAD];
    __shared__ float Bs[BK][BN + PAD];
    const float* A = J.A[br];
    const float* B = J.B[br];
    float*       C = J.C[br];
    const int lda = J.lda[br], ldb = J.ldb[br], ldc = J.ldc[br];
    const int M = J.M[br], N = J.N[br], K = J.K[br];
    const float alpha = J.alpha[br];
    const int h = zz & 3, bb_ = zz >> 2;
    A += (long)h * J.sAh[br] + (long)bb_ * J.sAb[br];
    B += (long)h * J.sBh[br] + (long)bb_ * J.sBb[br];
    C += (long)h * J.sCh[br] + (long)bb_ * J.sCb[br];
    const int nx = J.nx[br];
    const int row0 = (local / nx) * BM, col0 = (local % nx) * BN;

    const int tid = threadIdx.x;
    const int tx = tid & 15, ty = tid >> 4;

    // A tile loader: 128 rows x 8 k, one float4 per thread
    const int arow  = tid >> 1;
    const int akseg = (tid & 1) * 4;
    const int agr   = row0 + arow;
    // B tile loader
    const int brow  = tid >> 1;          // LAYB==0
    const int bkseg = (tid & 1) * 4;
    const int bkk   = tid >> 5;          // LAYB==1
    const int bn    = (tid & 31) * 4;

    float acc[8][8];
#pragma unroll
    for (int i = 0; i < 8; i++)
#pragma unroll
        for (int j = 0; j < 8; j++) acc[i][j] = 0.f;

    const int KT = (K + BK - 1) / BK;
    float4 av, bv;

    auto loadA = [&](int k0) {
        float4 v = make_float4(0.f, 0.f, 0.f, 0.f);
        int gk = k0 + akseg;
        if (agr < M && gk < K)
            v = *reinterpret_cast<const float4*>(A + (size_t)agr * lda + gk);
        return v;
    };
    auto loadB = [&](int k0) {
        float4 v = make_float4(0.f, 0.f, 0.f, 0.f);
        if (LAYB == 0) {
            int gk = k0 + bkseg, gn = col0 + brow;
            if (gn < N && gk < K)
                v = *reinterpret_cast<const float4*>(B + (size_t)gn * ldb + gk);
        } else {
            int gk = k0 + bkk, gn = col0 + bn;
            if (gk < K && gn < N)
                v = *reinterpret_cast<const float4*>(B + (size_t)gk * ldb + gn);
        }
        return v;
    };
    auto storeS = [&]() {
        As[akseg + 0][arow] = av.x; As[akseg + 1][arow] = av.y;
        As[akseg + 2][arow] = av.z; As[akseg + 3][arow] = av.w;
        if (LAYB == 0) {
            Bs[bkseg + 0][brow] = bv.x; Bs[bkseg + 1][brow] = bv.y;
            Bs[bkseg + 2][brow] = bv.z; Bs[bkseg + 3][brow] = bv.w;
        } else {
            *reinterpret_cast<float4*>(&Bs[bkk][bn]) = bv;
        }
    };
    auto compute = [&]() {
#pragma unroll
        for (int kk = 0; kk < BK; kk++) {
            float a[8], bq[8];
            *reinterpret_cast<float4*>(a)      = *reinterpret_cast<const float4*>(&As[kk][ty * 8]);
            *reinterpret_cast<float4*>(a + 4)  = *reinterpret_cast<const float4*>(&As[kk][ty * 8 + 4]);
            *reinterpret_cast<float4*>(bq)     = *reinterpret_cast<const float4*>(&Bs[kk][tx * 8]);
            *reinterpret_cast<float4*>(bq + 4) = *reinterpret_cast<const float4*>(&Bs[kk][tx * 8 + 4]);
#pragma unroll
            for (int i = 0; i < 8; i++)
#pragma unroll
                for (int j = 0; j < 8; j++)
                    acc[i][j] = fmaf(a[i], bq[j], acc[i][j]);
        }
    };

    av = loadA(0); bv = loadB(0);
    storeS();
    __syncthreads();
    for (int t = 1; t < KT; t++) {
        av = loadA(t * BK); bv = loadB(t * BK);
        compute();
        __syncthreads();
        storeS();
        __syncthreads();
    }
    compute();

#pragma unroll
    for (int i = 0; i < 8; i++)
#pragma unroll
        for (int j = 0; j < 8; j++) acc[i][j] *= alpha;

#pragma unroll
    for (int i = 0; i < 8; i++) {
        int gr = row0 + ty * 8 + i;
        if (gr >= M) continue;
        int gc0 = col0 + tx * 8;
        float* cp = C + (size_t)gr * ldc + gc0;
        if (gc0 + 7 < N) {
            *reinterpret_cast<float4*>(cp)     = *reinterpret_cast<float4*>(&acc[i][0]);
            *reinterpret_cast<float4*>(cp + 4) = *reinterpret_cast<float4*>(&acc[i][4]);
        } else {
#pragma unroll
            for (int j = 0; j < 8; j++)
                if (gc0 + j < N) cp[j] = acc[i][j];
        }
    }

    if (STATS) {
        float lsum = 0.f, lsq = 0.f;
#pragma unroll
        for (int i = 0; i < 8; i++) {
            float rm = -CUDART_INF_F;
            int gr = row0 + ty * 8 + i;
#pragma unroll
            for (int j = 0; j < 8; j++) {
                int gc = col0 + tx * 8 + j;
                if (gc < N) {
                    float v = acc[i][j];
                    lsum += v; lsq += v * v;
                    rm = fmaxf(rm, v);
                }
            }
#pragma unroll
            for (int m = 1; m < 16; m <<= 1)
                rm = fmaxf(rm, __shfl_xor_sync(0xffffffffu, rm, m, 16));
            if (tx == 0 && gr < M)
                atomicMax(&g_rowmaxi[J.rmoff[br] + zz * M + gr], f2ord(rm));
        }
        __shared__ float s1[256], s2[256];
        s1[tid] = lsum; s2[tid] = lsq;
        __syncthreads();
        for (int s = 128; s > 0; s >>= 1) {
            if (tid < s) { s1[tid] += s1[tid + s]; s2[tid] += s2[tid + s]; }
            __syncthreads();
        }
        if (tid == 0) {
            int pb = ((br * 64 + zz) * 32 + local) * 2;
            g_partial[pb] = s1[0];
            g_partial[pb + 1] = s2[0];
        }
    }
}

__device__ __forceinline__ int pick_branch(const Jobs& J, int bx) {
    int br = 0;
    if (bx >= J.bx0[1]) br = 1;
    if (bx >= J.bx0[2]) br = 2;
    if (bx >= J.bx0[3]) br = 3;
    return br;
}

__global__ __launch_bounds__(256, 2) void k_gemm_abT(Jobs J) {
    int bx = blockIdx.x, br = pick_branch(J, bx);
    gemm_core<0, false>(J, br, bx - J.bx0[br], blockIdx.z);
}
__global__ __launch_bounds__(256, 2) void k_gemm_ab(Jobs J) {
    int bx = blockIdx.x, br = pick_branch(J, bx);
    gemm_core<1, false>(J, br, bx - J.bx0[br], blockIdx.z);
}
__global__ __launch_bounds__(256, 2) void k_gemm_ab_stats(Jobs J) {
    int bx = blockIdx.x, br = pick_branch(J, bx);
    gemm_core<1, true>(J, br, bx - J.bx0[br], blockIdx.z);
}

// ---------------- small kernels ----------------------------------------------------
__global__ void k_initmax()
{
    int i = blockIdx.x * 256 + threadIdx.x;
    if (i < 64 * 960) g_rowmaxi[i] = 0x80000000;
}

__global__ void k_stats_final()
{
    int t = threadIdx.x;                    // 256 = 4 branches x 64 z
    int br = t >> 6, z = t & 63;
    const int nbk[4] = {8, 8, 16, 32};      // 8 * my tiles per (br,z)
    const int cs[4]  = {64, 128, 256, 512};
    float sum = 0.f, sq = 0.f;
    int base = (br * 64 + z) * 32;
    for (int s = 0; s < nbk[br]; s++) {
        sum += g_partial[(base + s) * 2 + 0];
        sq  += g_partial[(base + s) * 2 + 1];
    }
    float n = (float)cs[br] * 960.f;
    float m = sum / n;
    g_invstd[t] = rsqrtf(sq / n - m * m + 1e-5f);
}

// One block per score row: p <- softmax((p - mean)*invstd) computed as
// exp(p*invstd - max*invstd)/sum (InstanceNorm mean cancels by shift-invariance).
__global__ __launch_bounds__(256) void k_probs()
{
    int idx = blockIdx.x;                   // global row in [0, 61440)
    int br = (idx >= 4096) + (idx >= 12288) + (idx >= 28672);
    const int cs[4]   = {64, 128, 256, 512};
    const int base[4] = {0, 4096, 12288, 28672};
    const long soff[4] = {0, 64L*64*960, 64L*192*960, 64L*448*960};
    int local = idx - base[br];
    int z = local / cs[br];
    float is  = g_invstd[br * 64 + z];
    float off = ord2f(g_rowmaxi[idx]) * is;
    float* p = g_scores + soff[br] + (long)local * 960;

    int t = threadIdx.x;
    bool v3 = (t + 768) < 960;
    float e0 = __expf(p[t]       * is - off);
    float e1 = __expf(p[t + 256] * is - off);
    float e2 = __expf(p[t + 512] * is - off);
    float e3 = v3 ? __expf(p[t + 768] * is - off) : 0.f;

    __shared__ float sh[256];
    sh[t] = e0 + e1 + e2 + e3;
    __syncthreads();
    for (int s = 128; s > 0; s >>= 1) {
        if (t < s) sh[t] += sh[t + s];
        __syncthreads();
    }
    float rinv = 1.f / sh[0];
    p[t]       = e0 * rinv;
    p[t + 256] = e1 * rinv;
    p[t + 512] = e2 * rinv;
    if (v3) p[t + 768] = e3 * rinv;
}

// ctxm[b][n][d] = 0.25 * sum_h ctx[b*4+h][d][n]  (all branches merged via blockIdx.y)
__global__ void k_meanT_all()
{
    __shared__ float t[32][33];
    int by = blockIdx.y;
    int br = (by >= 2) + (by >= 6) + (by >= 14);
    const int cs[4]    = {64, 128, 256, 512};
    const int ybase[4] = {0, 2, 6, 14};
    const long ctxoff[4] = {0, 64L*64*196, 64L*192*196, 64L*448*196};
    const long cmoff[4]  = {0, 16L*196*64, 16L*196*192, 16L*196*448};
    int c = cs[br];
    int b  = blockIdx.z;
    int d0 = (by - ybase[br]) * 32, n0 = blockIdx.x * 32;
    const float* ctx = g_ctx + ctxoff[br];
    float* cm = g_ctxm + cmoff[br];
    int tx = threadIdx.x, ty = threadIdx.y;
    for (int i = ty; i < 32; i += 8) {
        int d = d0 + i, n = n0 + tx;
        float s = 0.f;
        if (n < 196) {
            for (int hh = 0; hh < 4; hh++)
                s += ctx[((size_t)(b * 4 + hh) * c + d) * 196 + n];
        }
        t[i][tx] = 0.25f * s;
    }
    __syncthreads();
    for (int i = ty; i < 32; i += 8) {
        int n = n0 + i, d = d0 + tx;
        if (n < 196) cm[((size_t)b * 196 + n) * c + d] = t[tx][i];
    }
}

// ---------------- launch -------------------------------------------------------------
extern "C" void kernel_launch(void* const* d_in, const int* in_sizes, int n_in,
                              void* d_out, int out_size)
{
    (void)in_sizes; (void)n_in; (void)out_size;
    const float* emb[4]  = {(const float*)d_in[0], (const float*)d_in[1],
                            (const float*)d_in[2], (const float*)d_in[3]};
    const float* emb_all = (const float*)d_in[4];
    const float* Wq[4]   = {(const float*)d_in[5], (const float*)d_in[6],
                            (const float*)d_in[7], (const float*)d_in[8]};
    const float* Wk      = (const float*)d_in[9];
    const float* Wv      = (const float*)d_in[10];
    const float* Wo[4]   = {(const float*)d_in[11], (const float*)d_in[12],
                            (const float*)d_in[13], (const float*)d_in[14]};
    float* out = (float*)d_out;

    float *pK, *pVt, *pQt, *pSc, *pCx, *pCm;
    cudaGetSymbolAddress((void**)&pK,  g_K);
    cudaGetSymbolAddress((void**)&pVt, g_Vt);
    cudaGetSymbolAddress((void**)&pQt, g_Qt);
    cudaGetSymbolAddress((void**)&pSc, g_scores);
    cudaGetSymbolAddress((void**)&pCx, g_ctx);
    cudaGetSymbolAddress((void**)&pCm, g_ctxm);

    const int   Cs[4]    = {64, 128, 256, 512};
    const int   cumc[4]  = {0, 64, 192, 448};
    const int   my[4]    = {1, 1, 2, 4};
    const int   rmbase[4]= {0, 4096, 12288, 28672};
    const int   offs[4]  = {0, 16*196*64, 16*196*(64+128), 16*196*(64+128+256)};
    const float SCALE    = 0.03227486121839514f;   // 1/sqrt(960)
    const int   IMAXI    = 0x7fffffff;

    k_initmax<<<(64 * 960 + 255) / 256, 256>>>();

    // ---- merged K/Vt projections: 2 jobs ----
    {
        Jobs J = {};
        // job0: K[z][196][960] = emb_all[b] * Wk[h]^T
        J.A[0]=emb_all; J.sAh[0]=0;        J.sAb[0]=196L*960; J.lda[0]=960;
        J.B[0]=Wk;      J.sBh[0]=960L*960; J.sBb[0]=0;        J.ldb[0]=960;
        J.C[0]=pK;      J.sCh[0]=196L*960; J.sCb[0]=4L*196*960; J.ldc[0]=960;
        J.M[0]=196; J.N[0]=960; J.K[0]=960; J.alpha[0]=1.f; J.nx[0]=8; J.bx0[0]=0;
        // job1: Vt[z][960][196] = Wv[h] * emb_all[b]^T
        J.A[1]=Wv;      J.sAh[1]=960L*960; J.sAb[1]=0;        J.lda[1]=960;
        J.B[1]=emb_all; J.sBh[1]=0;        J.sBb[1]=196L*960; J.ldb[1]=960;
        J.C[1]=pVt;     J.sCh[1]=960L*196; J.sCb[1]=4L*960*196; J.ldc[1]=196;
        J.M[1]=960; J.N[1]=196; J.K[1]=960; J.alpha[1]=1.f; J.nx[1]=2; J.bx0[1]=16;
        J.bx0[2]=IMAXI; J.bx0[3]=IMAXI;
        k_gemm_abT<<<dim3(32, 1, 64), 256>>>(J);
    }

    // ---- merged Qt projections (4 jobs) ----
    {
        Jobs J = {};
        int bx = 0;
        for (int br = 0; br < 4; br++) {
            long c = Cs[br];
            J.A[br]=Wq[br];  J.sAh[br]=c*c;     J.sAb[br]=0;         J.lda[br]=(int)c;
            J.B[br]=emb[br]; J.sBh[br]=0;       J.sBb[br]=196L*c;    J.ldb[br]=(int)c;
            J.C[br]=pQt + 64L*196*cumc[br];
            J.sCh[br]=c*196; J.sCb[br]=4L*c*196; J.ldc[br]=196;
            J.M[br]=(int)c; J.N[br]=196; J.K[br]=(int)c; J.alpha[br]=1.f;
            J.nx[br]=2; J.bx0[br]=bx; bx += 2 * my[br];
        }
        k_gemm_abT<<<dim3(16, 1, 64), 256>>>(J);
    }

    // ---- merged scores GEMM + stats epilogue (4 jobs) ----
    {
        Jobs J = {};
        int bx = 0;
        for (int br = 0; br < 4; br++) {
            long c = Cs[br];
            J.A[br]=pQt + 64L*196*cumc[br];
            J.sAh[br]=c*196;    J.sAb[br]=4L*c*196;    J.lda[br]=196;
            J.B[br]=pK; J.sBh[br]=196L*960; J.sBb[br]=4L*196*960; J.ldb[br]=960;
            J.C[br]=pSc + 64L*960*cumc[br];
            J.sCh[br]=c*960;    J.sCb[br]=4L*c*960;    J.ldc[br]=960;
            J.M[br]=(int)c; J.N[br]=960; J.K[br]=196; J.alpha[br]=SCALE;
            J.nx[br]=8; J.bx0[br]=bx; J.rmoff[br]=rmbase[br]; bx += 8 * my[br];
        }
        k_gemm_ab_stats<<<dim3(64, 1, 64), 256>>>(J);
    }

    k_stats_final<<<1, 256>>>();
    k_probs<<<61440, 256>>>();

    // ---- merged ctx GEMM (4 jobs, plain — probs already normalized) ----
    {
        Jobs J = {};
        int bx = 0;
        for (int br = 0; br < 4; br++) {
            long c = Cs[br];
            J.A[br]=pSc + 64L*960*cumc[br];
            J.sAh[br]=c*960;    J.sAb[br]=4L*c*960;    J.lda[br]=960;
            J.B[br]=pVt; J.sBh[br]=960L*196; J.sBb[br]=4L*960*196; J.ldb[br]=196;
            J.C[br]=pCx + 64L*196*cumc[br];
            J.sCh[br]=c*196;    J.sCb[br]=4L*c*196;    J.ldc[br]=196;
            J.M[br]=(int)c; J.N[br]=196; J.K[br]=960; J.alpha[br]=1.f;
            J.nx[br]=2; J.bx0[br]=bx; bx += 2 * my[br];
        }
        k_gemm_ab<<<dim3(16, 1, 64), 256>>>(J);
    }

    k_meanT_all<<<dim3(7, 30, 16), dim3(32, 8)>>>();

    // ---- merged output projections (4 jobs, z=1) ----
    {
        Jobs J = {};
        int bx = 0;
        for (int br = 0; br < 4; br++) {
            long c = Cs[br];
            J.A[br]=pCm + 16L*196*cumc[br];
            J.sAh[br]=0; J.sAb[br]=0; J.lda[br]=(int)c;
            J.B[br]=Wo[br]; J.sBh[br]=0; J.sBb[br]=0; J.ldb[br]=(int)c;
            J.C[br]=out + offs[br]; J.sCh[br]=0; J.sCb[br]=0; J.ldc[br]=(int)c;
            J.M[br]=16*196; J.N[br]=(int)c; J.K[br]=(int)c; J.alpha[br]=1.f;
            int nxo = (Cs[br] + 127) / 128;
            J.nx[br]=nxo; J.bx0[br]=bx; bx += nxo * 25;
        }
        k_gemm_abT<<<dim3(200, 1, 1), 256>>>(J);
    }
}